// round 1
// baseline (speedup 1.0000x reference)
#include <cuda_runtime.h>
#include <cuda_bf16.h>

// Problem constants (fixed shapes from reference setup_inputs)
#define BB 4
#define NN 16384
#define PP 1024
#define CC 128
#define NS 64
#define R2 0.04f

// Scratch (allocations are forbidden; use __device__ globals)
__device__ float g_ftrans[(size_t)BB * NN * CC];   // features transposed to (B, N, C), 32 MB
__device__ int   g_idx[BB * PP * NS];              // masked gather indices (NN == pad)

// ---------------------------------------------------------------------------
// Kernel A: transpose features (B, C, N) -> (B, N, C)
// ---------------------------------------------------------------------------
__global__ void transpose_kernel(const float* __restrict__ f) {
    __shared__ float tile[32][33];
    const int b = blockIdx.z;
    const int nBase = blockIdx.x * 32;
    const int cBase = blockIdx.y * 32;
    const float* fb = f + (size_t)b * CC * NN;
    float* ob = g_ftrans + (size_t)b * NN * CC;
    const int tx = threadIdx.x, ty = threadIdx.y;  // 32 x 8
#pragma unroll
    for (int i = 0; i < 32; i += 8)
        tile[ty + i][tx] = fb[(size_t)(cBase + ty + i) * NN + nBase + tx];
    __syncthreads();
#pragma unroll
    for (int i = 0; i < 32; i += 8)
        ob[(size_t)(nBase + ty + i) * CC + cBase + tx] = tile[tx][ty + i];
}

// ---------------------------------------------------------------------------
// Kernel B: ball query — one warp per center, ordered compaction via ballot.
// Writes idx0 output (float) and masked indices to g_idx.
// ---------------------------------------------------------------------------
__global__ void __launch_bounds__(256) ballquery_kernel(
    const float* __restrict__ xyz, const float* __restrict__ new_xyz,
    float* __restrict__ out_idx) {
    __shared__ int sidx[8][NS];
    const int warp = threadIdx.x >> 5;
    const int lane = threadIdx.x & 31;
    const int p = blockIdx.x * 8 + warp;
    const int b = blockIdx.y;

    const float* xb = xyz + (size_t)b * NN * 3;
    const float qx = new_xyz[((size_t)b * PP + p) * 3 + 0];
    const float qy = new_xyz[((size_t)b * PP + p) * 3 + 1];
    const float qz = new_xyz[((size_t)b * PP + p) * 3 + 2];

    int cnt = 0;
    for (int base = 0; base < NN && cnt < NS; base += 32) {
        const int i = base + lane;
        // Match JAX f32 rounding exactly: no FMA contraction, left-to-right sum.
        const float dx = __fadd_rn(qx, -xb[i * 3 + 0]);
        const float dy = __fadd_rn(qy, -xb[i * 3 + 1]);
        const float dz = __fadd_rn(qz, -xb[i * 3 + 2]);
        const float d2 = __fadd_rn(__fadd_rn(__fmul_rn(dx, dx), __fmul_rn(dy, dy)),
                                   __fmul_rn(dz, dz));
        const bool hit = d2 < R2;
        const unsigned m = __ballot_sync(0xffffffffu, hit);
        const int pos = cnt + __popc(m & ((1u << lane) - 1u));
        if (hit && pos < NS) sidx[warp][pos] = i;
        cnt += __popc(m);
    }
    if (cnt > NS) cnt = NS;
    __syncwarp();

    const int first = (cnt > 0) ? sidx[warp][0] : NN;
    const size_t base = ((size_t)b * PP + p) * NS;
#pragma unroll
    for (int s = lane; s < NS; s += 32) {
        const int real = (s < cnt);
        const int v0 = real ? sidx[warp][s] : first;  // idx0 output (pad -> first)
        const int vm = real ? sidx[warp][s] : NN;     // masked gather index
        g_idx[base + s] = vm;
        out_idx[base + s] = (float)v0;
    }
}

// ---------------------------------------------------------------------------
// Kernel C: gather + group. One block per (b, p). Stage a 64x128 feature tile
// in smem (contiguous 512B reads from g_ftrans), then write channel-major,
// s-coalesced output. Also computes grouped_xyz / xyz_feature channels.
// ---------------------------------------------------------------------------
__global__ void __launch_bounds__(256) group_kernel(
    const float* __restrict__ xyz, const float* __restrict__ new_xyz,
    float* __restrict__ out) {
    __shared__ float ftile[NS][CC + 1];  // stride 129: conflict-free column reads
    __shared__ int sidx[NS];

    const int p = blockIdx.x;
    const int b = blockIdx.y;
    const int t = threadIdx.x;
    const int warp = t >> 5;
    const int lane = t & 31;

    if (t < NS) sidx[t] = g_idx[((size_t)b * PP + p) * NS + t];
    __syncthreads();

    // Stage: warp handles one s per iteration; 32 lanes x float4 = 128 channels.
#pragma unroll
    for (int s = warp; s < NS; s += 8) {
        const int n = sidx[s];
        float4 v = make_float4(0.f, 0.f, 0.f, 0.f);
        if (n < NN)
            v = *(const float4*)&g_ftrans[((size_t)b * NN + n) * CC + lane * 4];
        ftile[s][lane * 4 + 0] = v.x;
        ftile[s][lane * 4 + 1] = v.y;
        ftile[s][lane * 4 + 2] = v.z;
        ftile[s][lane * 4 + 3] = v.w;
    }
    __syncthreads();

    float* nf = out;                                        // new_features (B,131,P,NS)
    float* gx = out + (size_t)BB * 131 * PP * NS;           // grouped_xyz  (B,3,P,NS)

    const int s = t & 63;
    const int chRow = t >> 6;  // 0..3

    // Feature channels 3..130 of new_features
#pragma unroll 8
    for (int it = 0; it < CC / 4; ++it) {
        const int ch = it * 4 + chRow;
        nf[(((size_t)b * 131 + 3 + ch) * PP + p) * NS + s] = ftile[s][ch];
    }

    // xyz channels: grouped_xyz + xyz_feature (channels 0..2)
    if (t < 192) {
        const int c = t >> 6;  // 0..2
        const int n = sidx[s];
        const float q = new_xyz[((size_t)b * PP + p) * 3 + c];
        const float src = (n < NN) ? xyz[((size_t)b * NN + n) * 3 + c] : 1000000.0f;
        const float g = __fadd_rn(src, -q);
        gx[(((size_t)b * 3 + c) * PP + p) * NS + s] = g;
        const float xf = (g > 100000.0f) ? 0.0f : g;
        nf[(((size_t)b * 131 + c) * PP + p) * NS + s] = xf / 0.2f;
    }
}

// ---------------------------------------------------------------------------
extern "C" void kernel_launch(void* const* d_in, const int* in_sizes, int n_in,
                              void* d_out, int out_size) {
    const float* xyz      = (const float*)d_in[0];  // (B, N, 3)
    const float* new_xyz  = (const float*)d_in[1];  // (B, P, 3)
    const float* features = (const float*)d_in[2];  // (B, C, N)
    float* out = (float*)d_out;

    float* out_idx = out + (size_t)BB * 131 * PP * NS + (size_t)BB * 3 * PP * NS;

    transpose_kernel<<<dim3(NN / 32, CC / 32, BB), dim3(32, 8)>>>(features);
    ballquery_kernel<<<dim3(PP / 8, BB), 256>>>(xyz, new_xyz, out_idx);
    group_kernel<<<dim3(PP, BB), 256>>>(xyz, new_xyz, out);
}

// round 2
// speedup vs baseline: 2.6139x; 2.6139x over previous
#include <cuda_runtime.h>
#include <cuda_bf16.h>

// Problem constants (fixed shapes from reference setup_inputs)
#define BB 4
#define NN 16384
#define PP 1024
#define CC 128
#define NS 64
#define R2 0.04f
#define FST 65   // ftile row stride (odd -> conflict-free column STS)

// Scratch (allocations forbidden; __device__ global)
__device__ float g_ftrans[(size_t)BB * NN * CC];   // (B, N, C), 32 MB

// ---------------------------------------------------------------------------
// Kernel A: transpose features (B, C, N) -> (B, N, C)   [proven in R1]
// ---------------------------------------------------------------------------
__global__ void transpose_kernel(const float* __restrict__ f) {
    __shared__ float tile[32][33];
    const int b = blockIdx.z;
    const int nBase = blockIdx.x * 32;
    const int cBase = blockIdx.y * 32;
    const float* fb = f + (size_t)b * CC * NN;
    float* ob = g_ftrans + (size_t)b * NN * CC;
    const int tx = threadIdx.x, ty = threadIdx.y;  // 32 x 8
#pragma unroll
    for (int i = 0; i < 32; i += 8)
        tile[ty + i][tx] = fb[(size_t)(cBase + ty + i) * NN + nBase + tx];
    __syncthreads();
#pragma unroll
    for (int i = 0; i < 32; i += 8)
        ob[(size_t)(nBase + ty + i) * CC + cBase + tx] = tile[tx][ty + i];
}

// ---------------------------------------------------------------------------
// Kernel B (fused): block per (b, p).
//   Phase 1: block-wide ordered ball-query compaction (256 pts/iter).
//   Phase 2: gather feature rows into smem tile [ch][s] (stride 65).
//   Phase 3: STG.128 channel-major output along s; xyz channels scalar.
// ---------------------------------------------------------------------------
__global__ void __launch_bounds__(256) fused_kernel(
    const float* __restrict__ xyz, const float* __restrict__ new_xyz,
    float* __restrict__ out) {
    __shared__ float ftile[CC * FST];   // 33280 B
    __shared__ int sidx[NS];
    __shared__ int smidx[NS];
    __shared__ int wcnt[8];

    const int p = blockIdx.x;
    const int b = blockIdx.y;
    const int t = threadIdx.x;
    const int warp = t >> 5;
    const int lane = t & 31;

    const float qx = new_xyz[((size_t)b * PP + p) * 3 + 0];
    const float qy = new_xyz[((size_t)b * PP + p) * 3 + 1];
    const float qz = new_xyz[((size_t)b * PP + p) * 3 + 2];
    const float* xb = xyz + (size_t)b * NN * 3;

    // ---- Phase 1: ordered compaction, 256 points per iteration ----
    int cnt = 0;
    for (int base = 0; base < NN; base += 256) {
        const int i = base + t;
        // Match JAX f32 rounding exactly: no FMA contraction, left-to-right sum.
        const float dx = __fadd_rn(qx, -xb[i * 3 + 0]);
        const float dy = __fadd_rn(qy, -xb[i * 3 + 1]);
        const float dz = __fadd_rn(qz, -xb[i * 3 + 2]);
        const float d2 = __fadd_rn(__fadd_rn(__fmul_rn(dx, dx), __fmul_rn(dy, dy)),
                                   __fmul_rn(dz, dz));
        const bool hit = d2 < R2;
        const unsigned m = __ballot_sync(0xffffffffu, hit);
        if (lane == 0) wcnt[warp] = __popc(m);
        __syncthreads();
        int pre = cnt, total = 0;
#pragma unroll
        for (int w = 0; w < 8; w++) {
            const int c = wcnt[w];
            if (w < warp) pre += c;
            total += c;
        }
        const int pos = pre + __popc(m & ((1u << lane) - 1u));
        if (hit && pos < NS) sidx[pos] = i;
        cnt += total;
        __syncthreads();
        if (cnt >= NS) break;   // cnt uniform across block
    }
    const int cn = cnt < NS ? cnt : NS;

    // ---- idx output + masked gather indices ----
    float* out_idx = out + (size_t)BB * 131 * PP * NS + (size_t)BB * 3 * PP * NS;
    if (t < NS) {
        const int first = (cn > 0) ? sidx[0] : NN;
        const bool real = (t < cn);
        const int v0 = real ? sidx[t] : first;   // idx0 (pad -> first)
        smidx[t] = real ? sidx[t] : NN;          // masked (pad -> NN)
        out_idx[((size_t)b * PP + p) * NS + t] = (float)v0;
    }
    __syncthreads();

    // ---- Phase 2: gather 64 x 512B contiguous rows into ftile[ch][s] ----
    const float* fb = g_ftrans + (size_t)b * NN * CC;
    for (int s = warp; s < NS; s += 8) {
        const int n = smidx[s];
        if (n < NN) {
            const float* row = fb + (size_t)n * CC + lane;
#pragma unroll
            for (int j = 0; j < 4; j++)
                ftile[(lane + 32 * j) * FST + s] = row[32 * j];
        } else {
#pragma unroll
            for (int j = 0; j < 4; j++)
                ftile[(lane + 32 * j) * FST + s] = 0.0f;
        }
    }
    __syncthreads();

    // ---- Phase 3a: feature channels 3..130, STG.128 along s ----
    float* nfb = out + (((size_t)b * 131 + 3) * PP + p) * NS;
#pragma unroll
    for (int k = 0; k < 8; k++) {
        const int idx = t + 256 * k;     // 0..2047
        const int s4 = idx & 15;         // group of 4 s values
        const int ch = idx >> 4;         // 0..127
        const float* src = &ftile[ch * FST + s4 * 4];
        const float4 v = make_float4(src[0], src[1], src[2], src[3]);
        *(float4*)&nfb[(size_t)ch * PP * NS + s4 * 4] = v;
    }

    // ---- Phase 3b: grouped_xyz + xyz_feature channels ----
    if (t < 192) {
        const int s = t & 63;
        const int c = t >> 6;   // 0..2
        const int n = smidx[s];
        const float q = (c == 0) ? qx : ((c == 1) ? qy : qz);
        const float src = (n < NN) ? xb[n * 3 + c] : 1000000.0f;
        const float g = __fadd_rn(src, -q);
        float* gx = out + (size_t)BB * 131 * PP * NS;
        gx[(((size_t)b * 3 + c) * PP + p) * NS + s] = g;
        const float xf = (g > 100000.0f) ? 0.0f : g;
        out[(((size_t)b * 131 + c) * PP + p) * NS + s] = xf / 0.2f;
    }
}

// ---------------------------------------------------------------------------
extern "C" void kernel_launch(void* const* d_in, const int* in_sizes, int n_in,
                              void* d_out, int out_size) {
    const float* xyz      = (const float*)d_in[0];  // (B, N, 3)
    const float* new_xyz  = (const float*)d_in[1];  // (B, P, 3)
    const float* features = (const float*)d_in[2];  // (B, C, N)
    float* out = (float*)d_out;

    transpose_kernel<<<dim3(NN / 32, CC / 32, BB), dim3(32, 8)>>>(features);
    fused_kernel<<<dim3(PP, BB), 256>>>(xyz, new_xyz, out);
}